// round 3
// baseline (speedup 1.0000x reference)
#include <cuda_runtime.h>
#include <cuda_bf16.h>
#include <math.h>

// ---------------------------------------------------------------------------
// VectorQuantiser forward, GB300 sm_103a
// z [16,64,64,64] f32 (4194304 elems), embedding [1024,64] f32, embed_prob [1024]
// Tokens N = 16*64*64 = 65536, codes K = 1024, dim D = 64.
// Output (concatenated f32, reference return order):
//   z_q_out [4194304], loss [1], perplexity [1], new_embedding [65536],
//   embed_prob_new [1024], encoding_indices [65536]  -> total 4326402
// ---------------------------------------------------------------------------

#define N_TOK 65536
#define K_CODE 1024
#define D_DIM 64

#define OFF_ZQ   0
#define OFF_LOSS 4194304
#define OFF_PERP 4194305
#define OFF_EMB  4194306
#define OFF_EPN  4259842
#define OFF_ENC  4260866

// ---- scratch (static device memory; allocation-free) ----
__device__ float              g_e2[K_CODE];
__device__ unsigned long long g_cbest[256 * K_CODE];   // per-block per-code best
__device__ int                g_idx[N_TOK];            // per-token argmax code
__device__ int                g_closest[K_CODE];       // per-code argmax token
__device__ int                g_hist[K_CODE];
__device__ float              g_partial[16384];        // loss partials

// ---- helpers ----
__device__ __forceinline__ unsigned long long fma_f32x2(
    unsigned long long a, unsigned long long b, unsigned long long c) {
    unsigned long long d;
    asm("fma.rn.f32x2 %0, %1, %2, %3;" : "=l"(d) : "l"(a), "l"(b), "l"(c));
    return d;
}

// ---------------------------------------------------------------------------
// Kernel 1: prep — codebook squared norms + zero histogram
// ---------------------------------------------------------------------------
__global__ void vq_prep(const float* __restrict__ emb) {
    int k = blockIdx.x * 256 + threadIdx.x;   // grid 4 x 256 = 1024
    float s = 0.f;
    const float* e = emb + k * D_DIM;
#pragma unroll
    for (int j = 0; j < D_DIM; j++) s = fmaf(e[j], e[j], s);
    g_e2[k] = s;
    g_hist[k] = 0;
}

// ---------------------------------------------------------------------------
// Kernel 2: main — distance matrix + dual argmax.
// 256 blocks x 256 threads, 1 token/thread, all 1024 codes per block in
// 8 smem chunks of 128 codes. Packed f32x2 FMAs, z-row resident in regs.
// ---------------------------------------------------------------------------
__global__ void __launch_bounds__(256, 2) vq_main(
    const float* __restrict__ z, const float* __restrict__ emb) {
    __shared__ __align__(16) float sh_e[128 * D_DIM];   // 32 KB
    __shared__ float sh_e2[128];
    __shared__ unsigned long long sbest[128];

    const int tid = threadIdx.x;
    const int n = blockIdx.x * 256 + tid;
    const int b = n >> 12, p = n & 4095;
    const float* zb = z + ((size_t)b << 18) + p;        // channel stride 4096

    // Load z row (coalesced: consecutive threads -> consecutive p), pack pairs.
    unsigned long long zpk[32];
    float zn2 = 0.f;
#pragma unroll
    for (int t = 0; t < 32; t++) {
        float a0 = zb[(size_t)(2 * t) << 12];
        float a1 = zb[(size_t)(2 * t + 1) << 12];
        zn2 = fmaf(a0, a0, zn2);
        zn2 = fmaf(a1, a1, zn2);
        asm("mov.b64 %0, {%1, %2};" : "=l"(zpk[t]) : "f"(a0), "f"(a1));
    }
    const float nzn2 = -zn2;

    float bestv = -3.0e38f;
    int bestk = 0;
    const int lane = tid & 31;
    const int wbase = tid & ~31;

    for (int ch = 0; ch < 8; ch++) {
        // cooperative chunk copy: 128 codes * 64 f32 = 2048 float4
        const float4* src = (const float4*)(emb + (ch << 13));
        float4* dst = (float4*)sh_e;
#pragma unroll
        for (int r = 0; r < 8; r++) dst[tid + (r << 8)] = src[tid + (r << 8)];
        if (tid < 128) {
            sh_e2[tid] = g_e2[(ch << 7) + tid];
            sbest[tid] = 0ULL;
        }
        __syncthreads();

#pragma unroll 1
        for (int kc = 0; kc < 128; kc++) {
            const ulonglong2* ep = (const ulonglong2*)(sh_e + (kc << 6));
            unsigned long long a0 = 0ULL, a1 = 0ULL;     // (0.f,0.f)
#pragma unroll
            for (int t = 0; t < 8; t++) {
                ulonglong2 e01 = ep[2 * t];       // LDS.128 broadcast
                ulonglong2 e23 = ep[2 * t + 1];
                a0 = fma_f32x2(zpk[4 * t + 0], e01.x, a0);
                a1 = fma_f32x2(zpk[4 * t + 1], e01.y, a1);
                a0 = fma_f32x2(zpk[4 * t + 2], e23.x, a0);
                a1 = fma_f32x2(zpk[4 * t + 3], e23.y, a1);
            }
            float l0, h0, l1, h1;
            asm("mov.b64 {%0,%1}, %2;" : "=f"(l0), "=f"(h0) : "l"(a0));
            asm("mov.b64 {%0,%1}, %2;" : "=f"(l1), "=f"(h1) : "l"(a1));
            float dot = (l0 + h0) + (l1 + h1);
            // reference rounding chain: d = ((-zn2) - e2) + 2*dot, no fma fuse
            float t2 = __fsub_rn(nzn2, sh_e2[kc]);
            float d  = __fadd_rn(t2, __fmul_rn(2.0f, dot));
            int k = (ch << 7) + kc;

            // per-token argmax (ascending k, strict > => first max, like jnp)
            if (d > bestv) { bestv = d; bestk = k; }

            // per-code argmax over tokens: orderable key + redux + ballot
            unsigned u = __float_as_uint(d);
            u ^= ((unsigned)((int)u >> 31)) | 0x80000000u;
            unsigned wmax = __reduce_max_sync(0xFFFFFFFFu, u);
            unsigned ball = __ballot_sync(0xFFFFFFFFu, u == wmax);
            if (lane == 0) {
                int srcln = __ffs(ball) - 1;     // lowest lane = lowest token
                unsigned tok = (unsigned)(blockIdx.x * 256 + wbase + srcln);
                unsigned long long pk =
                    ((unsigned long long)wmax << 32) | (unsigned)(~tok);
                atomicMax(&sbest[kc], pk);       // ties -> larger ~tok = lower tok
            }
        }
        __syncthreads();
        if (tid < 128)
            g_cbest[(size_t)blockIdx.x * K_CODE + (ch << 7) + tid] = sbest[tid];
        __syncthreads();
    }
    g_idx[n] = bestk;
}

// ---------------------------------------------------------------------------
// Kernel 3: reduce per-code bests across the 256 blocks (deterministic max)
// ---------------------------------------------------------------------------
__global__ void vq_reduce_code() {
    int k = blockIdx.x * 256 + threadIdx.x;   // grid 4 x 256
    unsigned long long m = 0ULL;
    for (int bb = 0; bb < 256; bb++) {
        unsigned long long v = g_cbest[(size_t)bb * K_CODE + k];
        if (v > m) m = v;
    }
    g_closest[k] = (int)(~((unsigned)m));
}

// ---------------------------------------------------------------------------
// Kernel 4: histogram + encoding_indices output
// ---------------------------------------------------------------------------
__global__ void vq_hist_enc(float* __restrict__ out) {
    __shared__ int h[K_CODE];
    int tid = threadIdx.x;                    // grid 64 x 256, 4 tokens/thread
#pragma unroll
    for (int i = 0; i < 4; i++) h[i * 256 + tid] = 0;
    __syncthreads();
#pragma unroll
    for (int i = 0; i < 4; i++) {
        int n = blockIdx.x * 1024 + i * 256 + tid;
        int idx = g_idx[n];
        atomicAdd(&h[idx], 1);
        out[OFF_ENC + n] = (float)idx;
    }
    __syncthreads();
#pragma unroll
    for (int i = 0; i < 4; i++) {
        int v = h[i * 256 + tid];
        if (v) atomicAdd(&g_hist[i * 256 + tid], v);
    }
}

// ---------------------------------------------------------------------------
// Kernel 5: scalars (perplexity), embed_prob_new, new_embedding
// ---------------------------------------------------------------------------
__global__ void vq_scalars(float* __restrict__ out, const float* __restrict__ z,
                           const float* __restrict__ emb,
                           const float* __restrict__ prob) {
    __shared__ float red[1024];
    int t = threadIdx.x;                      // grid 1 x 1024
    float avg = (float)g_hist[t] * (1.0f / 65536.0f);   // exact /2^16
    red[t] = __fmul_rn(avg, logf(__fadd_rn(avg, 1e-10f)));
    __syncthreads();
    for (int s = 512; s > 0; s >>= 1) {
        if (t < s) red[t] += red[t + s];
        __syncthreads();
    }
    if (t == 0) out[OFF_PERP] = expf(-red[0]);

    float epn = __fadd_rn(__fmul_rn(prob[t], 0.99f), __fmul_rn(0.01f, avg));
    out[OFF_EPN + t] = epn;

    float a = __fmul_rn(epn, 1024.0f);
    a = __fmul_rn(a, 10.0f);
    a = a / 0.01f;
    float arg = __fsub_rn(-a, 1e-3f);
    float decay = expf(arg);
    float omd = __fsub_rn(1.0f, decay);

    int cn = g_closest[t];
    int cb = cn >> 12, cp = cn & 4095;
    const float* zb = z + ((size_t)cb << 18) + cp;
#pragma unroll 8
    for (int c = 0; c < D_DIM; c++) {
        float e = emb[t * D_DIM + c];
        float zc = zb[(size_t)c << 12];
        out[OFF_EMB + t * D_DIM + c] =
            __fadd_rn(__fmul_rn(e, omd), __fmul_rn(zc, decay));
    }
}

// ---------------------------------------------------------------------------
// Kernel 6: z_q_out (straight-through rounding replicated) + loss partials
// ---------------------------------------------------------------------------
__global__ void vq_zq_loss(float* __restrict__ out, const float* __restrict__ z,
                           const float* __restrict__ emb) {
    __shared__ float red[256];
    int i = blockIdx.x * 256 + threadIdx.x;   // grid 16384 x 256, i < 4194304
    int b = i >> 18;
    int c = (i >> 12) & 63;
    int p = i & 4095;
    int n = (b << 12) | p;
    int idx = g_idx[n];
    float ev = emb[(idx << 6) + c];
    float zv = z[i];
    float diff = __fsub_rn(ev, zv);
    out[OFF_ZQ + i] = __fadd_rn(zv, diff);    // zc + (z_q - zc), ref rounding
    red[threadIdx.x] = __fmul_rn(diff, diff);
    __syncthreads();
    for (int s = 128; s > 0; s >>= 1) {
        if (threadIdx.x < s) red[threadIdx.x] += red[threadIdx.x + s];
        __syncthreads();
    }
    if (threadIdx.x == 0) g_partial[blockIdx.x] = red[0];
}

// ---------------------------------------------------------------------------
// Kernel 7: deterministic loss reduction
// ---------------------------------------------------------------------------
__global__ void vq_loss_final(float* __restrict__ out) {
    __shared__ double red[256];
    int t = threadIdx.x;                      // grid 1 x 256
    double a = 0.0;
    for (int i = t; i < 16384; i += 256) a += (double)g_partial[i];
    red[t] = a;
    __syncthreads();
    for (int s = 128; s > 0; s >>= 1) {
        if (t < s) red[t] += red[t + s];
        __syncthreads();
    }
    if (t == 0)
        out[OFF_LOSS] = (float)(1.25 * red[0] / 4194304.0);  // (1+BETA)*mean
}

// ---------------------------------------------------------------------------
extern "C" void kernel_launch(void* const* d_in, const int* in_sizes, int n_in,
                              void* d_out, int out_size) {
    const float* z = nullptr;
    const float* emb = nullptr;
    const float* prob = nullptr;
    for (int i = 0; i < n_in; i++) {
        if (in_sizes[i] == 4194304) z = (const float*)d_in[i];
        else if (in_sizes[i] == 65536) emb = (const float*)d_in[i];
        else if (in_sizes[i] == 1024) prob = (const float*)d_in[i];
    }
    float* out = (float*)d_out;

    vq_prep<<<4, 256>>>(emb);
    vq_main<<<256, 256>>>(z, emb);
    vq_reduce_code<<<4, 256>>>();
    vq_hist_enc<<<64, 256>>>(out);
    vq_scalars<<<1, 1024>>>(out, z, emb, prob);
    vq_zq_loss<<<16384, 256>>>(out, z, emb);
    vq_loss_final<<<1, 256>>>(out);
}

// round 4
// speedup vs baseline: 1.2856x; 1.2856x over previous
#include <cuda_runtime.h>
#include <cuda_bf16.h>
#include <math.h>

// ---------------------------------------------------------------------------
// VectorQuantiser forward, GB300 sm_103a
// z [16,64,64,64] f32 (4194304), embedding [1024,64] f32, embed_prob [1024]
// Tokens N = 65536, codes K = 1024, dim D = 64.
// Output (f32, reference order): z_q_out [4194304], loss [1], perplexity [1],
//   new_embedding [65536], embed_prob_new [1024], encoding_indices [65536]
// ---------------------------------------------------------------------------

#define N_TOK 65536
#define K_CODE 1024
#define D_DIM 64

#define OFF_ZQ   0
#define OFF_LOSS 4194304
#define OFF_PERP 4194305
#define OFF_EMB  4194306
#define OFF_EPN  4259842
#define OFF_ENC  4260866

// ---- scratch (static device memory; allocation-free) ----
__device__ float              g_e2[K_CODE];
__device__ unsigned long long g_cbest[K_CODE * 256];   // [code][block] transposed
__device__ __align__(16) int  g_idx[N_TOK];
__device__ int                g_closest[K_CODE];
__device__ int                g_hist[K_CODE];
__device__ float              g_decay[K_CODE];
__device__ float              g_partial[4096];

// ---- helpers ----
__device__ __forceinline__ unsigned long long fma_f32x2(
    unsigned long long a, unsigned long long b, unsigned long long c) {
    unsigned long long d;
    asm("fma.rn.f32x2 %0, %1, %2, %3;" : "=l"(d) : "l"(a), "l"(b), "l"(c));
    return d;
}

// ---------------------------------------------------------------------------
// Kernel 1: prep — codebook squared norms (R3 chain) + zero histogram
// ---------------------------------------------------------------------------
__global__ void vq_prep(const float* __restrict__ emb) {
    int k = blockIdx.x * 256 + threadIdx.x;   // grid 4 x 256
    float s = 0.f;
    const float* e = emb + k * D_DIM;
#pragma unroll
    for (int j = 0; j < D_DIM; j++) s = fmaf(e[j], e[j], s);
    g_e2[k] = s;
    g_hist[k] = 0;
}

// ---------------------------------------------------------------------------
// Kernel 2: main — distances + dual argmax + enc output + histogram.
// 256 blocks x 256 threads, 1 token/thread, 8 smem chunks of 128 codes.
// Numerics chain identical to the R3-passing kernel.
// ---------------------------------------------------------------------------
__global__ void __launch_bounds__(256, 2) vq_main(
    const float* __restrict__ z, const float* __restrict__ emb,
    float* __restrict__ out) {
    __shared__ __align__(16) float sh_e[128 * D_DIM];   // 32 KB
    __shared__ float sh_e2[128];
    __shared__ __align__(16) unsigned long long sbest[128];
    __shared__ int sh_hist[K_CODE];

    const int tid = threadIdx.x;
    const int n = blockIdx.x * 256 + tid;
    const int b = n >> 12, p = n & 4095;
    const float* zb = z + ((size_t)b << 18) + p;        // channel stride 4096

    const unsigned sb_base = (unsigned)__cvta_generic_to_shared(sbest);

#pragma unroll
    for (int i = 0; i < 4; i++) sh_hist[tid + i * 256] = 0;

    // Load z row (coalesced across threads), pack pairs. R3 zn2 chain.
    unsigned long long zpk[32];
    float zn2 = 0.f;
#pragma unroll
    for (int t = 0; t < 32; t++) {
        float a0 = zb[(size_t)(2 * t) << 12];
        float a1 = zb[(size_t)(2 * t + 1) << 12];
        zn2 = fmaf(a0, a0, zn2);
        zn2 = fmaf(a1, a1, zn2);
        asm("mov.b64 %0, {%1, %2};" : "=l"(zpk[t]) : "f"(a0), "f"(a1));
    }
    const float nzn2 = -zn2;
    const unsigned ntok = ~((unsigned)n);

    // token argmax kept as orderable uint key (d < 0 always => key = ~bits)
    unsigned best_u = 0;
    int bestk = 0;

    for (int ch = 0; ch < 8; ch++) {
        const int kbase = ch << 7;
        const float4* src = (const float4*)(emb + (ch << 13));
        float4* dst = (float4*)sh_e;
#pragma unroll
        for (int r = 0; r < 8; r++) dst[tid + (r << 8)] = src[tid + (r << 8)];
        if (tid < 128) {
            sh_e2[tid] = g_e2[kbase + tid];
            sbest[tid] = 0ULL;
        }
        __syncthreads();

#pragma unroll 1
        for (int kc = 0; kc < 128; kc++) {
            // stale filter: current per-block best key (hi word), indep load
            unsigned stale = ((volatile const unsigned*)sbest)[2 * kc + 1];
            float e2 = sh_e2[kc];
            const ulonglong2* ep = (const ulonglong2*)(sh_e + (kc << 6));
            unsigned long long a0 = 0ULL, a1 = 0ULL;
#pragma unroll
            for (int t = 0; t < 8; t++) {
                ulonglong2 e01 = ep[2 * t];       // LDS.128 broadcast
                ulonglong2 e23 = ep[2 * t + 1];
                a0 = fma_f32x2(zpk[4 * t + 0], e01.x, a0);
                a1 = fma_f32x2(zpk[4 * t + 1], e01.y, a1);
                a0 = fma_f32x2(zpk[4 * t + 2], e23.x, a0);
                a1 = fma_f32x2(zpk[4 * t + 3], e23.y, a1);
            }
            float l0, h0, l1, h1;
            asm("mov.b64 {%0,%1}, %2;" : "=f"(l0), "=f"(h0) : "l"(a0));
            asm("mov.b64 {%0,%1}, %2;" : "=f"(l1), "=f"(h1) : "l"(a1));
            float dot = (l0 + h0) + (l1 + h1);          // R3 combine order
            float t2 = __fsub_rn(nzn2, e2);             // R3 d chain
            float d  = __fadd_rn(t2, __fmul_rn(2.0f, dot));

            unsigned u = ~__float_as_uint(d);           // d<0: monotone key
            if (u > best_u) { best_u = u; bestk = kbase + kc; }

            // per-code argmax over tokens: redux + predicated smem atomic,
            // branch-free (no BSSY).
            unsigned wmax = __reduce_max_sync(0xFFFFFFFFu, u);
            unsigned pass = (u == wmax) & (u >= stale);
            unsigned long long pk =
                ((unsigned long long)u << 32) | ntok;   // ties -> lowest tok
            asm volatile(
                "{\n\t.reg .pred p;\n\t.reg .u64 t;\n\t"
                "setp.ne.u32 p, %0, 0;\n\t"
                "@p atom.shared.max.u64 t, [%1], %2;\n\t}"
                :: "r"(pass), "r"(sb_base + kc * 8), "l"(pk));
        }
        __syncthreads();
        if (tid < 128)
            g_cbest[(size_t)(kbase + tid) * 256 + blockIdx.x] = sbest[tid];
        __syncthreads();
    }

    g_idx[n] = bestk;
    out[OFF_ENC + n] = (float)bestk;
    atomicAdd(&sh_hist[bestk], 1);
    __syncthreads();
#pragma unroll
    for (int i = 0; i < 4; i++) {
        int v = sh_hist[tid + i * 256];
        if (v) atomicAdd(&g_hist[tid + i * 256], v);
    }
}

// ---------------------------------------------------------------------------
// Kernel 3: per-code best across 256 blocks, coalesced + warp shuffle
// ---------------------------------------------------------------------------
__global__ void vq_reduce_code() {
    int k = blockIdx.x;                       // grid 1024 x 32
    int lane = threadIdx.x;
    unsigned long long m = 0ULL;
    const unsigned long long* row = g_cbest + (size_t)k * 256;
#pragma unroll
    for (int i = 0; i < 8; i++) {
        unsigned long long v = row[i * 32 + lane];
        if (v > m) m = v;
    }
#pragma unroll
    for (int s = 16; s > 0; s >>= 1) {
        unsigned long long o = __shfl_xor_sync(0xFFFFFFFFu, m, s);
        if (o > m) m = o;
    }
    if (lane == 0) g_closest[k] = (int)(~((unsigned)m));
}

// ---------------------------------------------------------------------------
// Kernel 4: perplexity, embed_prob_new, decay factors
// ---------------------------------------------------------------------------
__global__ void vq_scalars(float* __restrict__ out,
                           const float* __restrict__ prob) {
    __shared__ float red[1024];
    int t = threadIdx.x;                      // grid 1 x 1024
    float avg = (float)g_hist[t] * (1.0f / 65536.0f);   // exact /2^16
    red[t] = __fmul_rn(avg, logf(__fadd_rn(avg, 1e-10f)));
    __syncthreads();
    for (int s = 512; s > 0; s >>= 1) {
        if (t < s) red[t] += red[t + s];
        __syncthreads();
    }
    if (t == 0) out[OFF_PERP] = expf(-red[0]);

    float epn = __fadd_rn(__fmul_rn(prob[t], 0.99f), __fmul_rn(0.01f, avg));
    out[OFF_EPN + t] = epn;

    float a = __fmul_rn(epn, 1024.0f);
    a = __fmul_rn(a, 10.0f);
    a = a / 0.01f;
    float arg = __fsub_rn(-a, 1e-3f);
    g_decay[t] = expf(arg);
}

// ---------------------------------------------------------------------------
// Kernel 5: new_embedding — one block per code, parallel gather
// ---------------------------------------------------------------------------
__global__ void vq_new_emb(float* __restrict__ out, const float* __restrict__ z,
                           const float* __restrict__ emb) {
    int k = blockIdx.x;                       // grid 1024 x 64
    int c = threadIdx.x;
    float decay = g_decay[k];
    float omd = __fsub_rn(1.0f, decay);
    int cn = g_closest[k];
    int cb = cn >> 12, cp = cn & 4095;
    float zc = z[((size_t)cb << 18) + ((size_t)c << 12) + cp];
    float e = emb[k * D_DIM + c];
    out[OFF_EMB + k * D_DIM + c] =
        __fadd_rn(__fmul_rn(e, omd), __fmul_rn(zc, decay));
}

// ---------------------------------------------------------------------------
// Kernel 6: z_q_out (straight-through rounding) + loss partials, float4
// ---------------------------------------------------------------------------
__global__ void vq_zq_loss(float* __restrict__ out, const float* __restrict__ z,
                           const float* __restrict__ emb) {
    __shared__ float red[256];
    int i4 = blockIdx.x * 256 + threadIdx.x;  // grid 4096 x 256
    int i = i4 << 2;
    int c = (i >> 12) & 63;
    int n = ((i >> 18) << 12) | (i & 4095);
    int4 id4 = *(const int4*)(g_idx + n);
    float4 zv = *(const float4*)(z + i);
    float4 ev;
    ev.x = emb[(id4.x << 6) + c];
    ev.y = emb[(id4.y << 6) + c];
    ev.z = emb[(id4.z << 6) + c];
    ev.w = emb[(id4.w << 6) + c];
    float dx = __fsub_rn(ev.x, zv.x);
    float dy = __fsub_rn(ev.y, zv.y);
    float dz = __fsub_rn(ev.z, zv.z);
    float dw = __fsub_rn(ev.w, zv.w);
    float4 o;
    o.x = __fadd_rn(zv.x, dx);
    o.y = __fadd_rn(zv.y, dy);
    o.z = __fadd_rn(zv.z, dz);
    o.w = __fadd_rn(zv.w, dw);
    *(float4*)(out + OFF_ZQ + i) = o;
    red[threadIdx.x] = __fmul_rn(dx, dx) + __fmul_rn(dy, dy) +
                       __fmul_rn(dz, dz) + __fmul_rn(dw, dw);
    __syncthreads();
    for (int s = 128; s > 0; s >>= 1) {
        if (threadIdx.x < s) red[threadIdx.x] += red[threadIdx.x + s];
        __syncthreads();
    }
    if (threadIdx.x == 0) g_partial[blockIdx.x] = red[0];
}

// ---------------------------------------------------------------------------
// Kernel 7: deterministic loss reduction
// ---------------------------------------------------------------------------
__global__ void vq_loss_final(float* __restrict__ out) {
    __shared__ double red[256];
    int t = threadIdx.x;                      // grid 1 x 256
    double a = 0.0;
#pragma unroll
    for (int i = 0; i < 16; i++) a += (double)g_partial[i * 256 + t];
    red[t] = a;
    __syncthreads();
    for (int s = 128; s > 0; s >>= 1) {
        if (t < s) red[t] += red[t + s];
        __syncthreads();
    }
    if (t == 0)
        out[OFF_LOSS] = (float)(1.25 * red[0] / 4194304.0);  // (1+BETA)*mean
}

// ---------------------------------------------------------------------------
extern "C" void kernel_launch(void* const* d_in, const int* in_sizes, int n_in,
                              void* d_out, int out_size) {
    const float* z = nullptr;
    const float* emb = nullptr;
    const float* prob = nullptr;
    for (int i = 0; i < n_in; i++) {
        if (in_sizes[i] == 4194304) z = (const float*)d_in[i];
        else if (in_sizes[i] == 65536) emb = (const float*)d_in[i];
        else if (in_sizes[i] == 1024) prob = (const float*)d_in[i];
    }
    float* out = (float*)d_out;

    vq_prep<<<4, 256>>>(emb);
    vq_main<<<256, 256>>>(z, emb, out);
    vq_reduce_code<<<1024, 32>>>();
    vq_scalars<<<1, 1024>>>(out, prob);
    vq_new_emb<<<1024, 64>>>(out, z, emb);
    vq_zq_loss<<<4096, 256>>>(out, z, emb);
    vq_loss_final<<<1, 256>>>(out);
}

// round 5
// speedup vs baseline: 1.6089x; 1.2514x over previous
#include <cuda_runtime.h>
#include <cuda_bf16.h>
#include <math.h>

// ---------------------------------------------------------------------------
// VectorQuantiser forward, GB300 sm_103a
// z [16,64,64,64] f32 (4194304), embedding [1024,64] f32, embed_prob [1024]
// Tokens N = 65536, codes K = 1024, dim D = 64.
// Output (f32, reference order): z_q_out [4194304], loss [1], perplexity [1],
//   new_embedding [65536], embed_prob_new [1024], encoding_indices [65536]
// ---------------------------------------------------------------------------

#define N_TOK 65536
#define K_CODE 1024
#define D_DIM 64

#define OFF_ZQ   0
#define OFF_LOSS 4194304
#define OFF_PERP 4194305
#define OFF_EMB  4194306
#define OFF_EPN  4259842
#define OFF_ENC  4260866

// ---- scratch (static device memory; allocation-free) ----
__device__ float              g_e2[K_CODE];
__device__ unsigned long long g_cbest[K_CODE * 256];   // [code][block]
__device__ __align__(16) int  g_idx[N_TOK];
__device__ int                g_closest[K_CODE];
__device__ int                g_hist[K_CODE];
__device__ float              g_decay[K_CODE];
__device__ float              g_partial[4096];

// ---- helpers ----
__device__ __forceinline__ unsigned long long fma_f32x2(
    unsigned long long a, unsigned long long b, unsigned long long c) {
    unsigned long long d;
    asm("fma.rn.f32x2 %0, %1, %2, %3;" : "=l"(d) : "l"(a), "l"(b), "l"(c));
    return d;
}

// ---------------------------------------------------------------------------
// Kernel 1: prep — codebook squared norms (frozen chain) + zero histogram
// ---------------------------------------------------------------------------
__global__ void vq_prep(const float* __restrict__ emb) {
    int k = blockIdx.x * 256 + threadIdx.x;   // grid 4 x 256
    float s = 0.f;
    const float* e = emb + k * D_DIM;
#pragma unroll
    for (int j = 0; j < D_DIM; j++) s = fmaf(e[j], e[j], s);
    g_e2[k] = s;
    g_hist[k] = 0;
}

// ---------------------------------------------------------------------------
// Kernel 2: main — distances + dual argmax + enc + histogram.
// 256 blocks x 128 threads, TWO tokens/thread (n, n+32768): the 16 LDS.128
// per code now feed 64 FFMA2 (2 tokens), halving the LDS stream that bound R4.
// Numerics chain per token is bit-identical to the R3/R4-passing kernels.
// ---------------------------------------------------------------------------
__global__ void __launch_bounds__(128, 2) vq_main(
    const float* __restrict__ z, const float* __restrict__ emb,
    float* __restrict__ out) {
    __shared__ __align__(16) float sh_e[128 * D_DIM];   // 32 KB
    __shared__ float sh_e2[128];
    __shared__ __align__(16) unsigned long long sbest[128];
    __shared__ int sh_hist[K_CODE];

    const int tid = threadIdx.x;
    const int n0 = blockIdx.x * 128 + tid;              // 0..32767
    const int n1 = n0 + 32768;                          // 32768..65535
    const float* zb0 = z + ((size_t)(n0 >> 12) << 18) + (n0 & 4095);
    const float* zb1 = zb0 + ((size_t)8 << 18);         // +8 batches

    const unsigned sb_base = (unsigned)__cvta_generic_to_shared(sbest);

#pragma unroll
    for (int i = 0; i < 8; i++) sh_hist[tid + i * 128] = 0;

    // Load both z rows (coalesced), pack pairs. Frozen zn2 chain per token.
    unsigned long long zpk0[32], zpk1[32];
    float zn2a = 0.f, zn2b = 0.f;
#pragma unroll
    for (int t = 0; t < 32; t++) {
        float a0 = zb0[(size_t)(2 * t) << 12];
        float a1 = zb0[(size_t)(2 * t + 1) << 12];
        zn2a = fmaf(a0, a0, zn2a);
        zn2a = fmaf(a1, a1, zn2a);
        asm("mov.b64 %0, {%1, %2};" : "=l"(zpk0[t]) : "f"(a0), "f"(a1));
        float c0 = zb1[(size_t)(2 * t) << 12];
        float c1 = zb1[(size_t)(2 * t + 1) << 12];
        zn2b = fmaf(c0, c0, zn2b);
        zn2b = fmaf(c1, c1, zn2b);
        asm("mov.b64 %0, {%1, %2};" : "=l"(zpk1[t]) : "f"(c0), "f"(c1));
    }
    const float nzn20 = -zn2a;
    const float nzn21 = -zn2b;
    const unsigned ntok0 = ~((unsigned)n0);
    const unsigned ntok1 = ~((unsigned)n1);

    unsigned best_u0 = 0, best_u1 = 0;
    int bestk0 = 0, bestk1 = 0;

    for (int ch = 0; ch < 8; ch++) {
        const int kbase = ch << 7;
        const float4* src = (const float4*)(emb + (ch << 13));
        float4* dst = (float4*)sh_e;
#pragma unroll
        for (int r = 0; r < 16; r++) dst[tid + (r << 7)] = src[tid + (r << 7)];
        sh_e2[tid] = g_e2[kbase + tid];
        sbest[tid] = 0ULL;
        __syncthreads();

#pragma unroll 1
        for (int kc = 0; kc < 128; kc++) {
            float e2 = sh_e2[kc];
            const ulonglong2* ep = (const ulonglong2*)(sh_e + (kc << 6));
            unsigned long long a0 = 0ULL, a1 = 0ULL;    // token0
            unsigned long long b0 = 0ULL, b1 = 0ULL;    // token1
#pragma unroll
            for (int t = 0; t < 8; t++) {
                ulonglong2 e01 = ep[2 * t];       // LDS.128 broadcast
                ulonglong2 e23 = ep[2 * t + 1];
                a0 = fma_f32x2(zpk0[4 * t + 0], e01.x, a0);
                a1 = fma_f32x2(zpk0[4 * t + 1], e01.y, a1);
                b0 = fma_f32x2(zpk1[4 * t + 0], e01.x, b0);
                b1 = fma_f32x2(zpk1[4 * t + 1], e01.y, b1);
                a0 = fma_f32x2(zpk0[4 * t + 2], e23.x, a0);
                a1 = fma_f32x2(zpk0[4 * t + 3], e23.y, a1);
                b0 = fma_f32x2(zpk1[4 * t + 2], e23.x, b0);
                b1 = fma_f32x2(zpk1[4 * t + 3], e23.y, b1);
            }
            float l0, h0, l1, h1, m0, g0, m1, g1;
            asm("mov.b64 {%0,%1}, %2;" : "=f"(l0), "=f"(h0) : "l"(a0));
            asm("mov.b64 {%0,%1}, %2;" : "=f"(l1), "=f"(h1) : "l"(a1));
            asm("mov.b64 {%0,%1}, %2;" : "=f"(m0), "=f"(g0) : "l"(b0));
            asm("mov.b64 {%0,%1}, %2;" : "=f"(m1), "=f"(g1) : "l"(b1));
            float dot0 = (l0 + h0) + (l1 + h1);         // frozen combine
            float dot1 = (m0 + g0) + (m1 + g1);
            float d0 = __fadd_rn(__fsub_rn(nzn20, e2), __fmul_rn(2.0f, dot0));
            float d1 = __fadd_rn(__fsub_rn(nzn21, e2), __fmul_rn(2.0f, dot1));
            int k = kbase + kc;

            unsigned u0 = ~__float_as_uint(d0);         // d<0: monotone key
            unsigned u1 = ~__float_as_uint(d1);
            if (u0 > best_u0) { best_u0 = u0; bestk0 = k; }
            if (u1 > best_u1) { best_u1 = u1; bestk1 = k; }

            // per-code argmax over tokens (u0 first => lower token on ties)
            unsigned uc = u0 > u1 ? u0 : u1;
            unsigned wmax = __reduce_max_sync(0xFFFFFFFFu, uc);
            unsigned tokn = (u0 == wmax) ? ntok0 : ntok1;
            unsigned pass = (uc == wmax);
            unsigned long long pk = ((unsigned long long)wmax << 32) | tokn;
            asm volatile(
                "{\n\t.reg .pred p;\n\t.reg .u64 t;\n\t"
                "setp.ne.u32 p, %0, 0;\n\t"
                "@p atom.shared.max.u64 t, [%1], %2;\n\t}"
                :: "r"(pass), "r"(sb_base + kc * 8), "l"(pk));
        }
        __syncthreads();
        g_cbest[(size_t)(kbase + tid) * 256 + blockIdx.x] = sbest[tid];
        __syncthreads();
    }

    g_idx[n0] = bestk0;
    g_idx[n1] = bestk1;
    out[OFF_ENC + n0] = (float)bestk0;
    out[OFF_ENC + n1] = (float)bestk1;
    atomicAdd(&sh_hist[bestk0], 1);
    atomicAdd(&sh_hist[bestk1], 1);
    __syncthreads();
#pragma unroll
    for (int i = 0; i < 8; i++) {
        int v = sh_hist[tid + i * 128];
        if (v) atomicAdd(&g_hist[tid + i * 128], v);
    }
}

// ---------------------------------------------------------------------------
// Kernel 3: per-code best across 256 blocks, coalesced + warp shuffle
// ---------------------------------------------------------------------------
__global__ void vq_reduce_code() {
    int k = blockIdx.x;                       // grid 1024 x 32
    int lane = threadIdx.x;
    unsigned long long m = 0ULL;
    const unsigned long long* row = g_cbest + (size_t)k * 256;
#pragma unroll
    for (int i = 0; i < 8; i++) {
        unsigned long long v = row[i * 32 + lane];
        if (v > m) m = v;
    }
#pragma unroll
    for (int s = 16; s > 0; s >>= 1) {
        unsigned long long o = __shfl_xor_sync(0xFFFFFFFFu, m, s);
        if (o > m) m = o;
    }
    if (lane == 0) g_closest[k] = (int)(~((unsigned)m));
}

// ---------------------------------------------------------------------------
// Kernel 4: perplexity, embed_prob_new, decay factors
// ---------------------------------------------------------------------------
__global__ void vq_scalars(float* __restrict__ out,
                           const float* __restrict__ prob) {
    __shared__ float red[1024];
    int t = threadIdx.x;                      // grid 1 x 1024
    float avg = (float)g_hist[t] * (1.0f / 65536.0f);   // exact /2^16
    red[t] = __fmul_rn(avg, logf(__fadd_rn(avg, 1e-10f)));
    __syncthreads();
    for (int s = 512; s > 0; s >>= 1) {
        if (t < s) red[t] += red[t + s];
        __syncthreads();
    }
    if (t == 0) out[OFF_PERP] = expf(-red[0]);

    float epn = __fadd_rn(__fmul_rn(prob[t], 0.99f), __fmul_rn(0.01f, avg));
    out[OFF_EPN + t] = epn;

    float a = __fmul_rn(epn, 1024.0f);
    a = __fmul_rn(a, 10.0f);
    a = a / 0.01f;
    float arg = __fsub_rn(-a, 1e-3f);
    g_decay[t] = expf(arg);
}

// ---------------------------------------------------------------------------
// Kernel 5: new_embedding — one block per code, parallel gather
// ---------------------------------------------------------------------------
__global__ void vq_new_emb(float* __restrict__ out, const float* __restrict__ z,
                           const float* __restrict__ emb) {
    int k = blockIdx.x;                       // grid 1024 x 64
    int c = threadIdx.x;
    float decay = g_decay[k];
    float omd = __fsub_rn(1.0f, decay);
    int cn = g_closest[k];
    int cb = cn >> 12, cp = cn & 4095;
    float zc = z[((size_t)cb << 18) + ((size_t)c << 12) + cp];
    float e = emb[k * D_DIM + c];
    out[OFF_EMB + k * D_DIM + c] =
        __fadd_rn(__fmul_rn(e, omd), __fmul_rn(zc, decay));
}

// ---------------------------------------------------------------------------
// Kernel 6: z_q_out (straight-through rounding) + loss partials, float4
// ---------------------------------------------------------------------------
__global__ void vq_zq_loss(float* __restrict__ out, const float* __restrict__ z,
                           const float* __restrict__ emb) {
    __shared__ float red[256];
    int i4 = blockIdx.x * 256 + threadIdx.x;  // grid 4096 x 256
    int i = i4 << 2;
    int c = (i >> 12) & 63;
    int n = ((i >> 18) << 12) | (i & 4095);
    int4 id4 = *(const int4*)(g_idx + n);
    float4 zv = *(const float4*)(z + i);
    float4 ev;
    ev.x = emb[(id4.x << 6) + c];
    ev.y = emb[(id4.y << 6) + c];
    ev.z = emb[(id4.z << 6) + c];
    ev.w = emb[(id4.w << 6) + c];
    float dx = __fsub_rn(ev.x, zv.x);
    float dy = __fsub_rn(ev.y, zv.y);
    float dz = __fsub_rn(ev.z, zv.z);
    float dw = __fsub_rn(ev.w, zv.w);
    float4 o;
    o.x = __fadd_rn(zv.x, dx);
    o.y = __fadd_rn(zv.y, dy);
    o.z = __fadd_rn(zv.z, dz);
    o.w = __fadd_rn(zv.w, dw);
    *(float4*)(out + OFF_ZQ + i) = o;
    red[threadIdx.x] = __fmul_rn(dx, dx) + __fmul_rn(dy, dy) +
                       __fmul_rn(dz, dz) + __fmul_rn(dw, dw);
    __syncthreads();
    for (int s = 128; s > 0; s >>= 1) {
        if (threadIdx.x < s) red[threadIdx.x] += red[threadIdx.x + s];
        __syncthreads();
    }
    if (threadIdx.x == 0) g_partial[blockIdx.x] = red[0];
}

// ---------------------------------------------------------------------------
// Kernel 7: deterministic loss reduction
// ---------------------------------------------------------------------------
__global__ void vq_loss_final(float* __restrict__ out) {
    __shared__ double red[256];
    int t = threadIdx.x;                      // grid 1 x 256
    double a = 0.0;
#pragma unroll
    for (int i = 0; i < 16; i++) a += (double)g_partial[i * 256 + t];
    red[t] = a;
    __syncthreads();
    for (int s = 128; s > 0; s >>= 1) {
        if (t < s) red[t] += red[t + s];
        __syncthreads();
    }
    if (t == 0)
        out[OFF_LOSS] = (float)(1.25 * red[0] / 4194304.0);  // (1+BETA)*mean
}

// ---------------------------------------------------------------------------
extern "C" void kernel_launch(void* const* d_in, const int* in_sizes, int n_in,
                              void* d_out, int out_size) {
    const float* z = nullptr;
    const float* emb = nullptr;
    const float* prob = nullptr;
    for (int i = 0; i < n_in; i++) {
        if (in_sizes[i] == 4194304) z = (const float*)d_in[i];
        else if (in_sizes[i] == 65536) emb = (const float*)d_in[i];
        else if (in_sizes[i] == 1024) prob = (const float*)d_in[i];
    }
    float* out = (float*)d_out;

    vq_prep<<<4, 256>>>(emb);
    vq_main<<<256, 128>>>(z, emb, out);
    vq_reduce_code<<<1024, 32>>>();
    vq_scalars<<<1, 1024>>>(out, prob);
    vq_new_emb<<<1024, 64>>>(out, z, emb);
    vq_zq_loss<<<4096, 256>>>(out, z, emb);
    vq_loss_final<<<1, 256>>>(out);
}